// round 3
// baseline (speedup 1.0000x reference)
#include <cuda_runtime.h>
#include <cuda_bf16.h>
#include <cstdint>
#include <math.h>

// ---------------------------------------------------------------------------
// GroupedGLU via mma.sync (HMMA) bf16x3-split GEMMs, ldmatrix + 2 CTA/SM.
//   prep:   x fp32 -> x_hi/x_lo bf16 ; W fp32 [R][C] -> W^T bf16 hi/lo [C][R]
//   gemm1:  z_gate,z_up = x @ Wg, x @ Wu ; h = silu(zg)*zu -> h_hi/h_lo bf16
//   gemm2:  y = h @ Wd -> fp32 out
// Each GEMM: 3 passes a_hi*b_hi + a_lo*b_hi + a_hi*b_lo  (drops lo*lo ~2^-16)
// ---------------------------------------------------------------------------

#define T_TOK   131072
#define DMODEL  256
#define DFF_    1024
#define NG      8
#define TPG     (T_TOK / NG)
#define SA2     40            // smem row stride in bf16 elems (32 data + 8 pad)
#define SA2B    80            // bytes

__device__ __nv_bfloat16 g_x_hi[(size_t)T_TOK * DMODEL];
__device__ __nv_bfloat16 g_x_lo[(size_t)T_TOK * DMODEL];
__device__ __nv_bfloat16 g_h_hi[(size_t)T_TOK * DFF_];
__device__ __nv_bfloat16 g_h_lo[(size_t)T_TOK * DFF_];
__device__ __nv_bfloat16 g_wg_hi[(size_t)NG * DFF_ * DMODEL];
__device__ __nv_bfloat16 g_wg_lo[(size_t)NG * DFF_ * DMODEL];
__device__ __nv_bfloat16 g_wu_hi[(size_t)NG * DFF_ * DMODEL];
__device__ __nv_bfloat16 g_wu_lo[(size_t)NG * DFF_ * DMODEL];
__device__ __nv_bfloat16 g_wd_hi[(size_t)NG * DMODEL * DFF_];
__device__ __nv_bfloat16 g_wd_lo[(size_t)NG * DMODEL * DFF_];

// ------------------------------- helpers -----------------------------------

__device__ __forceinline__ uint32_t smaddr(const void* p) {
    return (uint32_t)__cvta_generic_to_shared(p);
}

__device__ __forceinline__ void cp16(uint32_t dst, const void* src) {
    asm volatile("cp.async.cg.shared.global [%0], [%1], 16;" :: "r"(dst), "l"(src));
}
#define CP_COMMIT() asm volatile("cp.async.commit_group;" ::: "memory")
#define CP_WAIT1()  asm volatile("cp.async.wait_group 1;" ::: "memory")
#define CP_WAIT0()  asm volatile("cp.async.wait_group 0;" ::: "memory")

__device__ __forceinline__ void ldm_x4(uint32_t addr, uint32_t* r) {
    asm volatile("ldmatrix.sync.aligned.m8n8.x4.shared.b16 {%0,%1,%2,%3}, [%4];"
        : "=r"(r[0]), "=r"(r[1]), "=r"(r[2]), "=r"(r[3]) : "r"(addr));
}

__device__ __forceinline__ void mma16816(float* c, const uint32_t* a,
                                         uint32_t b0, uint32_t b1) {
    asm volatile(
        "mma.sync.aligned.m16n8k16.row.col.f32.bf16.bf16.f32 "
        "{%0,%1,%2,%3}, {%4,%5,%6,%7}, {%8,%9}, {%0,%1,%2,%3};"
        : "+f"(c[0]), "+f"(c[1]), "+f"(c[2]), "+f"(c[3])
        : "r"(a[0]), "r"(a[1]), "r"(a[2]), "r"(a[3]), "r"(b0), "r"(b1));
}

__device__ __forceinline__ void split2(float vx, float vy, uint32_t& hi, uint32_t& lo) {
    __nv_bfloat16 hx = __float2bfloat16(vx);
    __nv_bfloat16 hy = __float2bfloat16(vy);
    float rx = vx - __bfloat162float(hx);
    float ry = vy - __bfloat162float(hy);
    __nv_bfloat16 lx = __float2bfloat16(rx);
    __nv_bfloat16 ly = __float2bfloat16(ry);
    hi = ((uint32_t)__bfloat16_as_ushort(hy) << 16) | (uint32_t)__bfloat16_as_ushort(hx);
    lo = ((uint32_t)__bfloat16_as_ushort(ly) << 16) | (uint32_t)__bfloat16_as_ushort(lx);
}

__device__ __forceinline__ float silu_f(float z) {
    return z / (1.0f + __expf(-z));
}

// ----------------------------- prep kernel ---------------------------------
// blocks [0, 6144): weight transpose+split; blocks [6144, 22528): x split
#define W_BLOCKS 6144
#define X_BLOCKS 16384

__global__ void __launch_bounds__(256) prep_kernel(
    const float* __restrict__ x, const float* __restrict__ wg,
    const float* __restrict__ wu, const float* __restrict__ wd) {
    __shared__ float tile[32][33];
    const int bid = blockIdx.x;
    const int tid = threadIdx.x;

    if (bid >= W_BLOCKS) {
        size_t e0 = ((size_t)(bid - W_BLOCKS) * 256 + tid) * 8;
        #pragma unroll
        for (int j = 0; j < 2; j++) {
            float4 v = *(const float4*)&x[e0 + j * 4];
            uint32_t h0, l0, h1, l1;
            split2(v.x, v.y, h0, l0);
            split2(v.z, v.w, h1, l1);
            *(uint2*)&g_x_hi[e0 + j * 4] = make_uint2(h0, h1);
            *(uint2*)&g_x_lo[e0 + j * 4] = make_uint2(l0, l1);
        }
        return;
    }

    const int which = bid / 2048;
    const int rem = bid % 2048;
    const int g = rem >> 8;
    const int t = rem & 255;
    int R, C;
    const float* in;
    __nv_bfloat16 *oh, *ol;
    if (which == 0)      { R = DMODEL; C = DFF_;  in = wg; oh = g_wg_hi; ol = g_wg_lo; }
    else if (which == 1) { R = DMODEL; C = DFF_;  in = wu; oh = g_wu_hi; ol = g_wu_lo; }
    else                 { R = DFF_;  C = DMODEL; in = wd; oh = g_wd_hi; ol = g_wd_lo; }
    const int tilesC = C / 32;
    const int c0 = (t % tilesC) * 32, r0 = (t / tilesC) * 32;
    const float* src = in + (size_t)g * R * C;
    __nv_bfloat16* dh = oh + (size_t)g * R * C;
    __nv_bfloat16* dl = ol + (size_t)g * R * C;
    const int tx = tid & 31, ty = tid >> 5;
    #pragma unroll
    for (int j = ty; j < 32; j += 8)
        tile[j][tx] = src[(size_t)(r0 + j) * C + c0 + tx];
    __syncthreads();
    #pragma unroll
    for (int j = ty; j < 32; j += 8) {
        float v = tile[tx][j];
        __nv_bfloat16 h = __float2bfloat16(v);
        float r = v - __bfloat162float(h);
        size_t o = (size_t)(c0 + j) * R + r0 + tx;
        dh[o] = h;
        dl[o] = __float2bfloat16(r);
    }
}

// --------------------------- GEMM1: gate/up --------------------------------
// block 128 tok x 64 dff (gate AND up), K=256 in 8 chunks of 32.
// 8 warps = 4(M) x 2(N). Stage bytes: Ah 0, Al 10240, Bgh 20480, Bgl 25600,
// Buh 30720, Bul 35840; stage = 40960; double buffered = 81920.
#define G1_AH   0u
#define G1_AL   10240u
#define G1_BGH  20480u
#define G1_BGL  25600u
#define G1_BUH  30720u
#define G1_BUL  35840u
#define G1_STG  40960u
#define G1_SMEM (2 * 40960)

__global__ void __launch_bounds__(256, 2) gemm1_kernel() {
    extern __shared__ __align__(16) char sm[];
    const uint32_t sbase = smaddr(sm);
    const int tid  = threadIdx.x;
    const int lane = tid & 31, w = tid >> 5;
    const int wm = w & 3, wn = w >> 2;
    const int gID = lane >> 2, tig = lane & 3;
    const int m0 = blockIdx.y * 128;
    const int n0 = blockIdx.x * 64;
    const int g  = m0 / TPG;

    const __nv_bfloat16* wgh = g_wg_hi + ((size_t)g * DFF_ + n0) * DMODEL;
    const __nv_bfloat16* wgl = g_wg_lo + ((size_t)g * DFF_ + n0) * DMODEL;
    const __nv_bfloat16* wuh = g_wu_hi + ((size_t)g * DFF_ + n0) * DMODEL;
    const __nv_bfloat16* wul = g_wu_lo + ((size_t)g * DFF_ + n0) * DMODEL;

    // ldmatrix lane offsets (bytes)
    const uint32_t a_off = (uint32_t)(wm * 32 + (lane & 15)) * SA2B + ((lane >> 4) << 4);
    const uint32_t b_off = (uint32_t)(wn * 32 + (lane & 7) + ((lane >> 4) << 3)) * SA2B
                         + (((lane >> 3) & 1) << 4);
    // cp.async task decode
    const int arow = tid >> 2, aseg = tid & 3;

    float cg[2][4][4] = {}, cu[2][4][4] = {};

    auto issue = [&](int kc) {
        const uint32_t sb = sbase + (uint32_t)(kc & 1) * G1_STG;
        const int k0g = kc * 32;
        #pragma unroll
        for (int t = 0; t < 2; t++) {
            int row = arow + t * 64;
            size_t so = (size_t)(m0 + row) * DMODEL + k0g + aseg * 8;
            uint32_t d = sb + (uint32_t)row * SA2B + (uint32_t)aseg * 16;
            cp16(d + G1_AH, g_x_hi + so);
            cp16(d + G1_AL, g_x_lo + so);
        }
        {
            size_t so = (size_t)arow * DMODEL + k0g + aseg * 8;
            uint32_t d = sb + (uint32_t)arow * SA2B + (uint32_t)aseg * 16;
            cp16(d + G1_BGH, wgh + so);
            cp16(d + G1_BGL, wgl + so);
            cp16(d + G1_BUH, wuh + so);
            cp16(d + G1_BUL, wul + so);
        }
    };

    auto compute = [&](int kc) {
        const uint32_t sb = sbase + (uint32_t)(kc & 1) * G1_STG;
        #pragma unroll
        for (int k16 = 0; k16 < 2; k16++) {
            const uint32_t kb = (uint32_t)k16 * 32;
            uint32_t ah[2][4], al[2][4];
            #pragma unroll
            for (int mf = 0; mf < 2; mf++) {
                ldm_x4(sb + G1_AH + a_off + (uint32_t)mf * (16 * SA2B) + kb, ah[mf]);
                ldm_x4(sb + G1_AL + a_off + (uint32_t)mf * (16 * SA2B) + kb, al[mf]);
            }
            #pragma unroll
            for (int p = 0; p < 2; p++) {
                uint32_t bo = b_off + (uint32_t)p * (16 * SA2B) + kb;
                uint32_t bgh[4], bgl[4], buh[4], bul[4];
                ldm_x4(sb + G1_BGH + bo, bgh);
                ldm_x4(sb + G1_BGL + bo, bgl);
                ldm_x4(sb + G1_BUH + bo, buh);
                ldm_x4(sb + G1_BUL + bo, bul);
                #pragma unroll
                for (int s = 0; s < 2; s++) {
                    int nf = p * 2 + s;
                    #pragma unroll
                    for (int mf = 0; mf < 2; mf++) {
                        mma16816(cg[mf][nf], ah[mf], bgh[2*s], bgh[2*s+1]);
                        mma16816(cu[mf][nf], ah[mf], buh[2*s], buh[2*s+1]);
                        mma16816(cg[mf][nf], al[mf], bgh[2*s], bgh[2*s+1]);
                        mma16816(cu[mf][nf], al[mf], buh[2*s], buh[2*s+1]);
                        mma16816(cg[mf][nf], ah[mf], bgl[2*s], bgl[2*s+1]);
                        mma16816(cu[mf][nf], ah[mf], bul[2*s], bul[2*s+1]);
                    }
                }
            }
        }
    };

    issue(0); CP_COMMIT();
    #pragma unroll 1
    for (int kc = 0; kc < 8; kc++) {
        if (kc < 7) { issue(kc + 1); CP_COMMIT(); CP_WAIT1(); }
        else        { CP_WAIT0(); }
        __syncthreads();
        compute(kc);
        __syncthreads();
    }

    #pragma unroll
    for (int mf = 0; mf < 2; mf++) {
        #pragma unroll
        for (int nf = 0; nf < 4; nf++) {
            int r0 = m0 + wm * 32 + mf * 16 + gID;
            int c0 = n0 + wn * 32 + nf * 8 + tig * 2;
            float h0 = silu_f(cg[mf][nf][0]) * cu[mf][nf][0];
            float h1 = silu_f(cg[mf][nf][1]) * cu[mf][nf][1];
            float h2 = silu_f(cg[mf][nf][2]) * cu[mf][nf][2];
            float h3 = silu_f(cg[mf][nf][3]) * cu[mf][nf][3];
            uint32_t hi, lo;
            split2(h0, h1, hi, lo);
            *(uint32_t*)&g_h_hi[(size_t)r0 * DFF_ + c0] = hi;
            *(uint32_t*)&g_h_lo[(size_t)r0 * DFF_ + c0] = lo;
            split2(h2, h3, hi, lo);
            *(uint32_t*)&g_h_hi[(size_t)(r0 + 8) * DFF_ + c0] = hi;
            *(uint32_t*)&g_h_lo[(size_t)(r0 + 8) * DFF_ + c0] = lo;
        }
    }
}

// ----------------------------- GEMM2: down ---------------------------------
// block 128 tok x 128 dmodel, K=1024 in 32 chunks of 32.
// 8 warps = 4(M) x 2(N), warp N=64. Stage bytes: Ah 0, Al 10240, Bh 20480,
// Bl 30720; stage = 40960; double buffered = 81920.
#define G2_AH   0u
#define G2_AL   10240u
#define G2_BH   20480u
#define G2_BL   30720u
#define G2_STG  40960u
#define G2_SMEM (2 * 40960)

__global__ void __launch_bounds__(256, 2) gemm2_kernel(float* __restrict__ out) {
    extern __shared__ __align__(16) char sm[];
    const uint32_t sbase = smaddr(sm);
    const int tid  = threadIdx.x;
    const int lane = tid & 31, w = tid >> 5;
    const int wm = w & 3, wn = w >> 2;
    const int gID = lane >> 2, tig = lane & 3;
    const int m0 = blockIdx.y * 128;
    const int n0 = blockIdx.x * 128;
    const int g  = m0 / TPG;

    const __nv_bfloat16* wdh = g_wd_hi + ((size_t)g * DMODEL + n0) * DFF_;
    const __nv_bfloat16* wdl = g_wd_lo + ((size_t)g * DMODEL + n0) * DFF_;

    const uint32_t a_off = (uint32_t)(wm * 32 + (lane & 15)) * SA2B + ((lane >> 4) << 4);
    const uint32_t b_off = (uint32_t)(wn * 64 + (lane & 7) + ((lane >> 4) << 3)) * SA2B
                         + (((lane >> 3) & 1) << 4);
    const int arow = tid >> 2, aseg = tid & 3;

    float c[2][8][4] = {};

    auto issue = [&](int kc) {
        const uint32_t sb = sbase + (uint32_t)(kc & 1) * G2_STG;
        const int k0g = kc * 32;
        #pragma unroll
        for (int t = 0; t < 2; t++) {
            int row = arow + t * 64;
            size_t soA = (size_t)(m0 + row) * DFF_ + k0g + aseg * 8;
            size_t soB = (size_t)row * DFF_ + k0g + aseg * 8;
            uint32_t d = sb + (uint32_t)row * SA2B + (uint32_t)aseg * 16;
            cp16(d + G2_AH, g_h_hi + soA);
            cp16(d + G2_AL, g_h_lo + soA);
            cp16(d + G2_BH, wdh + soB);
            cp16(d + G2_BL, wdl + soB);
        }
    };

    auto compute = [&](int kc) {
        const uint32_t sb = sbase + (uint32_t)(kc & 1) * G2_STG;
        #pragma unroll
        for (int k16 = 0; k16 < 2; k16++) {
            const uint32_t kb = (uint32_t)k16 * 32;
            uint32_t ah[2][4], al[2][4];
            #pragma unroll
            for (int mf = 0; mf < 2; mf++) {
                ldm_x4(sb + G2_AH + a_off + (uint32_t)mf * (16 * SA2B) + kb, ah[mf]);
                ldm_x4(sb + G2_AL + a_off + (uint32_t)mf * (16 * SA2B) + kb, al[mf]);
            }
            #pragma unroll
            for (int p = 0; p < 4; p++) {
                uint32_t bo = b_off + (uint32_t)p * (16 * SA2B) + kb;
                uint32_t bh[4], bl[4];
                ldm_x4(sb + G2_BH + bo, bh);
                ldm_x4(sb + G2_BL + bo, bl);
                #pragma unroll
                for (int s = 0; s < 2; s++) {
                    int nf = p * 2 + s;
                    #pragma unroll
                    for (int mf = 0; mf < 2; mf++) {
                        mma16816(c[mf][nf], ah[mf], bh[2*s], bh[2*s+1]);
                        mma16816(c[mf][nf], al[mf], bh[2*s], bh[2*s+1]);
                        mma16816(c[mf][nf], ah[mf], bl[2*s], bl[2*s+1]);
                    }
                }
            }
        }
    };

    issue(0); CP_COMMIT();
    #pragma unroll 1
    for (int kc = 0; kc < 32; kc++) {
        if (kc < 31) { issue(kc + 1); CP_COMMIT(); CP_WAIT1(); }
        else         { CP_WAIT0(); }
        __syncthreads();
        compute(kc);
        __syncthreads();
    }

    #pragma unroll
    for (int mf = 0; mf < 2; mf++) {
        #pragma unroll
        for (int nf = 0; nf < 8; nf++) {
            int r0 = m0 + wm * 32 + mf * 16 + gID;
            int c0 = n0 + wn * 64 + nf * 8 + tig * 2;
            float2 v0 = { c[mf][nf][0], c[mf][nf][1] };
            float2 v1 = { c[mf][nf][2], c[mf][nf][3] };
            *(float2*)&out[(size_t)r0 * DMODEL + c0] = v0;
            *(float2*)&out[(size_t)(r0 + 8) * DMODEL + c0] = v1;
        }
    }
}

// ------------------------------- launch -------------------------------------
extern "C" void kernel_launch(void* const* d_in, const int* in_sizes, int n_in,
                              void* d_out, int out_size) {
    const float* x  = (const float*)d_in[0];
    const float* wg = (const float*)d_in[1];
    const float* wu = (const float*)d_in[2];
    const float* wd = (const float*)d_in[3];
    // d_in[4] = offs: uniform groups by construction (reference reshapes by T/G)

    cudaFuncSetAttribute(gemm1_kernel, cudaFuncAttributeMaxDynamicSharedMemorySize, G1_SMEM);
    cudaFuncSetAttribute(gemm2_kernel, cudaFuncAttributeMaxDynamicSharedMemorySize, G2_SMEM);

    prep_kernel<<<W_BLOCKS + X_BLOCKS, 256>>>(x, wg, wu, wd);
    gemm1_kernel<<<dim3(DFF_ / 64, T_TOK / 128), 256, G1_SMEM>>>();
    gemm2_kernel<<<dim3(DMODEL / 128, T_TOK / 128), 256, G2_SMEM>>>((float*)d_out);
}

// round 4
// speedup vs baseline: 1.1785x; 1.1785x over previous
#include <cuda_runtime.h>
#include <cuda_bf16.h>
#include <cstdint>
#include <math.h>

// ---------------------------------------------------------------------------
// GroupedGLU via mma.sync (HMMA) bf16x3-split GEMMs.
// R4: R2 structure (1 CTA/SM, K-chunk 64, 2-stage) + ldmatrix.x4 fragments.
//   prep:   x fp32 -> x_hi/x_lo bf16 ; W fp32 [R][C] -> W^T bf16 hi/lo [C][R]
//   gemm1:  z_gate,z_up = x @ Wg, x @ Wu ; h = silu(zg)*zu -> h_hi/h_lo bf16
//   gemm2:  y = h @ Wd -> fp32 out
// ---------------------------------------------------------------------------

#define T_TOK   131072
#define DMODEL  256
#define DFF_    1024
#define NG      8
#define TPG     (T_TOK / NG)
#define SAE     72            // smem row stride in bf16 elems (64 data + 8 pad)
#define SAB     144           // bytes

__device__ __nv_bfloat16 g_x_hi[(size_t)T_TOK * DMODEL];
__device__ __nv_bfloat16 g_x_lo[(size_t)T_TOK * DMODEL];
__device__ __nv_bfloat16 g_h_hi[(size_t)T_TOK * DFF_];
__device__ __nv_bfloat16 g_h_lo[(size_t)T_TOK * DFF_];
__device__ __nv_bfloat16 g_wg_hi[(size_t)NG * DFF_ * DMODEL];
__device__ __nv_bfloat16 g_wg_lo[(size_t)NG * DFF_ * DMODEL];
__device__ __nv_bfloat16 g_wu_hi[(size_t)NG * DFF_ * DMODEL];
__device__ __nv_bfloat16 g_wu_lo[(size_t)NG * DFF_ * DMODEL];
__device__ __nv_bfloat16 g_wd_hi[(size_t)NG * DMODEL * DFF_];
__device__ __nv_bfloat16 g_wd_lo[(size_t)NG * DMODEL * DFF_];

// ------------------------------- helpers -----------------------------------

__device__ __forceinline__ uint32_t smaddr(const void* p) {
    return (uint32_t)__cvta_generic_to_shared(p);
}

__device__ __forceinline__ void cp16(uint32_t dst, const void* src) {
    asm volatile("cp.async.cg.shared.global [%0], [%1], 16;" :: "r"(dst), "l"(src));
}
#define CP_COMMIT() asm volatile("cp.async.commit_group;" ::: "memory")
#define CP_WAIT1()  asm volatile("cp.async.wait_group 1;" ::: "memory")
#define CP_WAIT0()  asm volatile("cp.async.wait_group 0;" ::: "memory")

__device__ __forceinline__ void ldm_x4(uint32_t addr, uint32_t* r) {
    asm volatile("ldmatrix.sync.aligned.m8n8.x4.shared.b16 {%0,%1,%2,%3}, [%4];"
        : "=r"(r[0]), "=r"(r[1]), "=r"(r[2]), "=r"(r[3]) : "r"(addr));
}

__device__ __forceinline__ void mma16816(float* c, const uint32_t* a,
                                         uint32_t b0, uint32_t b1) {
    asm volatile(
        "mma.sync.aligned.m16n8k16.row.col.f32.bf16.bf16.f32 "
        "{%0,%1,%2,%3}, {%4,%5,%6,%7}, {%8,%9}, {%0,%1,%2,%3};"
        : "+f"(c[0]), "+f"(c[1]), "+f"(c[2]), "+f"(c[3])
        : "r"(a[0]), "r"(a[1]), "r"(a[2]), "r"(a[3]), "r"(b0), "r"(b1));
}

__device__ __forceinline__ void split2(float vx, float vy, uint32_t& hi, uint32_t& lo) {
    __nv_bfloat16 hx = __float2bfloat16(vx);
    __nv_bfloat16 hy = __float2bfloat16(vy);
    float rx = vx - __bfloat162float(hx);
    float ry = vy - __bfloat162float(hy);
    __nv_bfloat16 lx = __float2bfloat16(rx);
    __nv_bfloat16 ly = __float2bfloat16(ry);
    hi = ((uint32_t)__bfloat16_as_ushort(hy) << 16) | (uint32_t)__bfloat16_as_ushort(hx);
    lo = ((uint32_t)__bfloat16_as_ushort(ly) << 16) | (uint32_t)__bfloat16_as_ushort(lx);
}

__device__ __forceinline__ float silu_f(float z) {
    return z / (1.0f + __expf(-z));
}

// ----------------------------- prep kernel ---------------------------------
#define W_BLOCKS 6144
#define X_BLOCKS 16384

__global__ void __launch_bounds__(256) prep_kernel(
    const float* __restrict__ x, const float* __restrict__ wg,
    const float* __restrict__ wu, const float* __restrict__ wd) {
    __shared__ float tile[32][33];
    const int bid = blockIdx.x;
    const int tid = threadIdx.x;

    if (bid >= W_BLOCKS) {
        size_t e0 = ((size_t)(bid - W_BLOCKS) * 256 + tid) * 8;
        #pragma unroll
        for (int j = 0; j < 2; j++) {
            float4 v = *(const float4*)&x[e0 + j * 4];
            uint32_t h0, l0, h1, l1;
            split2(v.x, v.y, h0, l0);
            split2(v.z, v.w, h1, l1);
            *(uint2*)&g_x_hi[e0 + j * 4] = make_uint2(h0, h1);
            *(uint2*)&g_x_lo[e0 + j * 4] = make_uint2(l0, l1);
        }
        return;
    }

    const int which = bid / 2048;
    const int rem = bid % 2048;
    const int g = rem >> 8;
    const int t = rem & 255;
    int R, C;
    const float* in;
    __nv_bfloat16 *oh, *ol;
    if (which == 0)      { R = DMODEL; C = DFF_;  in = wg; oh = g_wg_hi; ol = g_wg_lo; }
    else if (which == 1) { R = DMODEL; C = DFF_;  in = wu; oh = g_wu_hi; ol = g_wu_lo; }
    else                 { R = DFF_;  C = DMODEL; in = wd; oh = g_wd_hi; ol = g_wd_lo; }
    const int tilesC = C / 32;
    const int c0 = (t % tilesC) * 32, r0 = (t / tilesC) * 32;
    const float* src = in + (size_t)g * R * C;
    __nv_bfloat16* dh = oh + (size_t)g * R * C;
    __nv_bfloat16* dl = ol + (size_t)g * R * C;
    const int tx = tid & 31, ty = tid >> 5;
    #pragma unroll
    for (int j = ty; j < 32; j += 8)
        tile[j][tx] = src[(size_t)(r0 + j) * C + c0 + tx];
    __syncthreads();
    #pragma unroll
    for (int j = ty; j < 32; j += 8) {
        float v = tile[tx][j];
        __nv_bfloat16 h = __float2bfloat16(v);
        float r = v - __bfloat162float(h);
        size_t o = (size_t)(c0 + j) * R + r0 + tx;
        dh[o] = h;
        dl[o] = __float2bfloat16(r);
    }
}

// --------------------------- GEMM1: gate/up --------------------------------
// block 128 tok x 64 dff (gate AND up), K=256 in 4 chunks of 64.
// 8 warps = 4(M) x 2(N). Stage elems (bf16): Ah 0, Al 9216, Bgh 18432,
// Bgl 23040, Buh 27648, Bul 32256; stage 36864 elems; double buffered.
#define G1_AH   0u
#define G1_AL   (9216u * 2)
#define G1_BGH  (18432u * 2)
#define G1_BGL  (23040u * 2)
#define G1_BUH  (27648u * 2)
#define G1_BUL  (32256u * 2)
#define G1_STG  (36864u * 2)
#define G1_SMEM (2 * 36864 * 2)

__global__ void __launch_bounds__(256, 1) gemm1_kernel() {
    extern __shared__ __align__(16) char sm[];
    const uint32_t sbase = smaddr(sm);
    const int tid  = threadIdx.x;
    const int lane = tid & 31, w = tid >> 5;
    const int wm = w & 3, wn = w >> 2;
    const int gID = lane >> 2, tig = lane & 3;
    const int m0 = blockIdx.y * 128;
    const int n0 = blockIdx.x * 64;
    const int g  = m0 / TPG;

    const __nv_bfloat16* wgh = g_wg_hi + ((size_t)g * DFF_ + n0) * DMODEL;
    const __nv_bfloat16* wgl = g_wg_lo + ((size_t)g * DFF_ + n0) * DMODEL;
    const __nv_bfloat16* wuh = g_wu_hi + ((size_t)g * DFF_ + n0) * DMODEL;
    const __nv_bfloat16* wul = g_wu_lo + ((size_t)g * DFF_ + n0) * DMODEL;

    // ldmatrix lane offsets (bytes); verified mapping (R3 rel_err identical)
    const uint32_t a_off = (uint32_t)(wm * 32 + (lane & 15)) * SAB + ((lane >> 4) << 4);
    const uint32_t b_off = (uint32_t)(wn * 32 + (lane & 7) + ((lane >> 4) << 3)) * SAB
                         + (((lane >> 3) & 1) << 4);
    const int arow = tid >> 3, aseg = tid & 7;   // A copy: 32 rows per pass
    const int brow = tid >> 3;                   // B copy: 32 rows per pass

    float cg[2][4][4] = {}, cu[2][4][4] = {};

    auto issue = [&](int kc) {
        const uint32_t sb = sbase + (uint32_t)(kc & 1) * G1_STG;
        const int k0g = kc * 64;
        #pragma unroll
        for (int t = 0; t < 4; t++) {
            int row = arow + t * 32;
            size_t so = (size_t)(m0 + row) * DMODEL + k0g + aseg * 8;
            uint32_t d = sb + (uint32_t)row * SAB + (uint32_t)aseg * 16;
            cp16(d + G1_AH, g_x_hi + so);
            cp16(d + G1_AL, g_x_lo + so);
        }
        #pragma unroll
        for (int t = 0; t < 2; t++) {
            int row = brow + t * 32;
            size_t so = (size_t)row * DMODEL + k0g + aseg * 8;
            uint32_t d = sb + (uint32_t)row * SAB + (uint32_t)aseg * 16;
            cp16(d + G1_BGH, wgh + so);
            cp16(d + G1_BGL, wgl + so);
            cp16(d + G1_BUH, wuh + so);
            cp16(d + G1_BUL, wul + so);
        }
    };

    auto compute = [&](int kc) {
        const uint32_t sb = sbase + (uint32_t)(kc & 1) * G1_STG;
        #pragma unroll
        for (int k16 = 0; k16 < 4; k16++) {
            const uint32_t kb = (uint32_t)k16 * 32;
            uint32_t ah[2][4], al[2][4];
            #pragma unroll
            for (int mf = 0; mf < 2; mf++) {
                ldm_x4(sb + G1_AH + a_off + (uint32_t)mf * (16 * SAB) + kb, ah[mf]);
                ldm_x4(sb + G1_AL + a_off + (uint32_t)mf * (16 * SAB) + kb, al[mf]);
            }
            #pragma unroll
            for (int p = 0; p < 2; p++) {
                uint32_t bo = b_off + (uint32_t)p * (16 * SAB) + kb;
                uint32_t bgh[4], bgl[4], buh[4], bul[4];
                ldm_x4(sb + G1_BGH + bo, bgh);
                ldm_x4(sb + G1_BGL + bo, bgl);
                ldm_x4(sb + G1_BUH + bo, buh);
                ldm_x4(sb + G1_BUL + bo, bul);
                #pragma unroll
                for (int s = 0; s < 2; s++) {
                    int nf = p * 2 + s;
                    #pragma unroll
                    for (int mf = 0; mf < 2; mf++) {
                        mma16816(cg[mf][nf], ah[mf], bgh[2*s], bgh[2*s+1]);
                        mma16816(cu[mf][nf], ah[mf], buh[2*s], buh[2*s+1]);
                        mma16816(cg[mf][nf], al[mf], bgh[2*s], bgh[2*s+1]);
                        mma16816(cu[mf][nf], al[mf], buh[2*s], buh[2*s+1]);
                        mma16816(cg[mf][nf], ah[mf], bgl[2*s], bgl[2*s+1]);
                        mma16816(cu[mf][nf], ah[mf], bul[2*s], bul[2*s+1]);
                    }
                }
            }
        }
    };

    issue(0); CP_COMMIT();
    #pragma unroll 1
    for (int kc = 0; kc < 4; kc++) {
        if (kc < 3) { issue(kc + 1); CP_COMMIT(); CP_WAIT1(); }
        else        { CP_WAIT0(); }
        __syncthreads();
        compute(kc);
        __syncthreads();
    }

    #pragma unroll
    for (int mf = 0; mf < 2; mf++) {
        #pragma unroll
        for (int nf = 0; nf < 4; nf++) {
            int r0 = m0 + wm * 32 + mf * 16 + gID;
            int c0 = n0 + wn * 32 + nf * 8 + tig * 2;
            float h0 = silu_f(cg[mf][nf][0]) * cu[mf][nf][0];
            float h1 = silu_f(cg[mf][nf][1]) * cu[mf][nf][1];
            float h2 = silu_f(cg[mf][nf][2]) * cu[mf][nf][2];
            float h3 = silu_f(cg[mf][nf][3]) * cu[mf][nf][3];
            uint32_t hi, lo;
            split2(h0, h1, hi, lo);
            *(uint32_t*)&g_h_hi[(size_t)r0 * DFF_ + c0] = hi;
            *(uint32_t*)&g_h_lo[(size_t)r0 * DFF_ + c0] = lo;
            split2(h2, h3, hi, lo);
            *(uint32_t*)&g_h_hi[(size_t)(r0 + 8) * DFF_ + c0] = hi;
            *(uint32_t*)&g_h_lo[(size_t)(r0 + 8) * DFF_ + c0] = lo;
        }
    }
}

// ----------------------------- GEMM2: down ---------------------------------
// block 128 tok x 128 dmodel, K=1024 in 16 chunks of 64.
// 8 warps = 4(M) x 2(N), warp N=64. Stage elems: Ah 0, Al 9216, Bh 18432,
// Bl 27648; stage 36864; double buffered.
#define G2_AH   0u
#define G2_AL   (9216u * 2)
#define G2_BH   (18432u * 2)
#define G2_BL   (27648u * 2)
#define G2_STG  (36864u * 2)
#define G2_SMEM (2 * 36864 * 2)

__global__ void __launch_bounds__(256, 1) gemm2_kernel(float* __restrict__ out) {
    extern __shared__ __align__(16) char sm[];
    const uint32_t sbase = smaddr(sm);
    const int tid  = threadIdx.x;
    const int lane = tid & 31, w = tid >> 5;
    const int wm = w & 3, wn = w >> 2;
    const int gID = lane >> 2, tig = lane & 3;
    const int m0 = blockIdx.y * 128;
    const int n0 = blockIdx.x * 128;
    const int g  = m0 / TPG;

    const __nv_bfloat16* wdh = g_wd_hi + ((size_t)g * DMODEL + n0) * DFF_;
    const __nv_bfloat16* wdl = g_wd_lo + ((size_t)g * DMODEL + n0) * DFF_;

    const uint32_t a_off = (uint32_t)(wm * 32 + (lane & 15)) * SAB + ((lane >> 4) << 4);
    const uint32_t b_off = (uint32_t)(wn * 64 + (lane & 7) + ((lane >> 4) << 3)) * SAB
                         + (((lane >> 3) & 1) << 4);
    const int arow = tid >> 3, aseg = tid & 7;

    float c[2][8][4] = {};

    auto issue = [&](int kc) {
        const uint32_t sb = sbase + (uint32_t)(kc & 1) * G2_STG;
        const int k0g = kc * 64;
        #pragma unroll
        for (int t = 0; t < 4; t++) {
            int row = arow + t * 32;
            size_t soA = (size_t)(m0 + row) * DFF_ + k0g + aseg * 8;
            size_t soB = (size_t)row * DFF_ + k0g + aseg * 8;
            uint32_t d = sb + (uint32_t)row * SAB + (uint32_t)aseg * 16;
            cp16(d + G2_AH, g_h_hi + soA);
            cp16(d + G2_AL, g_h_lo + soA);
            cp16(d + G2_BH, wdh + soB);
            cp16(d + G2_BL, wdl + soB);
        }
    };

    auto compute = [&](int kc) {
        const uint32_t sb = sbase + (uint32_t)(kc & 1) * G2_STG;
        #pragma unroll
        for (int k16 = 0; k16 < 4; k16++) {
            const uint32_t kb = (uint32_t)k16 * 32;
            uint32_t ah[2][4], al[2][4];
            #pragma unroll
            for (int mf = 0; mf < 2; mf++) {
                ldm_x4(sb + G2_AH + a_off + (uint32_t)mf * (16 * SAB) + kb, ah[mf]);
                ldm_x4(sb + G2_AL + a_off + (uint32_t)mf * (16 * SAB) + kb, al[mf]);
            }
            #pragma unroll
            for (int p = 0; p < 4; p++) {
                uint32_t bo = b_off + (uint32_t)p * (16 * SAB) + kb;
                uint32_t bh[4], bl[4];
                ldm_x4(sb + G2_BH + bo, bh);
                ldm_x4(sb + G2_BL + bo, bl);
                #pragma unroll
                for (int s = 0; s < 2; s++) {
                    int nf = p * 2 + s;
                    #pragma unroll
                    for (int mf = 0; mf < 2; mf++) {
                        mma16816(c[mf][nf], ah[mf], bh[2*s], bh[2*s+1]);
                        mma16816(c[mf][nf], al[mf], bh[2*s], bh[2*s+1]);
                        mma16816(c[mf][nf], ah[mf], bl[2*s], bl[2*s+1]);
                    }
                }
            }
        }
    };

    issue(0); CP_COMMIT();
    #pragma unroll 1
    for (int kc = 0; kc < 16; kc++) {
        if (kc < 15) { issue(kc + 1); CP_COMMIT(); CP_WAIT1(); }
        else         { CP_WAIT0(); }
        __syncthreads();
        compute(kc);
        __syncthreads();
    }

    #pragma unroll
    for (int mf = 0; mf < 2; mf++) {
        #pragma unroll
        for (int nf = 0; nf < 8; nf++) {
            int r0 = m0 + wm * 32 + mf * 16 + gID;
            int c0 = n0 + wn * 64 + nf * 8 + tig * 2;
            float2 v0 = { c[mf][nf][0], c[mf][nf][1] };
            float2 v1 = { c[mf][nf][2], c[mf][nf][3] };
            *(float2*)&out[(size_t)r0 * DMODEL + c0] = v0;
            *(float2*)&out[(size_t)(r0 + 8) * DMODEL + c0] = v1;
        }
    }
}

// ------------------------------- launch -------------------------------------
extern "C" void kernel_launch(void* const* d_in, const int* in_sizes, int n_in,
                              void* d_out, int out_size) {
    const float* x  = (const float*)d_in[0];
    const float* wg = (const float*)d_in[1];
    const float* wu = (const float*)d_in[2];
    const float* wd = (const float*)d_in[3];
    // d_in[4] = offs: uniform groups by construction (reference reshapes by T/G)

    cudaFuncSetAttribute(gemm1_kernel, cudaFuncAttributeMaxDynamicSharedMemorySize, G1_SMEM);
    cudaFuncSetAttribute(gemm2_kernel, cudaFuncAttributeMaxDynamicSharedMemorySize, G2_SMEM);

    prep_kernel<<<W_BLOCKS + X_BLOCKS, 256>>>(x, wg, wu, wd);
    gemm1_kernel<<<dim3(DFF_ / 64, T_TOK / 128), 256, G1_SMEM>>>();
    gemm2_kernel<<<dim3(DMODEL / 128, T_TOK / 128), 256, G2_SMEM>>>((float*)d_out);
}